// round 3
// baseline (speedup 1.0000x reference)
#include <cuda_runtime.h>
#include <cstdint>

#define NN 2048
#define EE 65536
#define CC 32

// Scratch (device globals — no allocation allowed)
__device__ float g_agg1[NN * CC];
__device__ float g_agg2[NN * CC];
__device__ float g_agg3[NN * CC];
__device__ float g_cnt[NN];
__device__ float g_h1[NN * CC];
__device__ float g_h2[NN * CC];
__device__ float g_h3[NN * CC];

// ---------------------------------------------------------------------------
// Zero scratch (must re-run every graph replay)
// ---------------------------------------------------------------------------
__global__ void zero_kernel() {
    int tid = blockIdx.x * blockDim.x + threadIdx.x;
    if (tid < NN * CC) {
        g_agg1[tid] = 0.f;
        g_agg2[tid] = 0.f;
        g_agg3[tid] = 0.f;
    }
    if (tid < NN) g_cnt[tid] = 0.f;
}

// ---------------------------------------------------------------------------
// Layer 1 edge pass (in_c = 1): w = relu(ea@W1 + b1); msg = x[src]*w
// Warp per edge, grid-stride. Also accumulates per-dst counts (lane 0).
// ---------------------------------------------------------------------------
__global__ void edge1_kernel(const float* __restrict__ x,
                             const float* __restrict__ ea,
                             const int* __restrict__ src,
                             const int* __restrict__ dst,
                             const float* __restrict__ W1,
                             const float* __restrict__ b1) {
    int lane = threadIdx.x & 31;
    int warp = (blockIdx.x * blockDim.x + threadIdx.x) >> 5;
    int nw = (gridDim.x * blockDim.x) >> 5;

    float w[6];
#pragma unroll
    for (int v = 0; v < 6; v++) w[v] = W1[v * CC + lane];
    float bb = b1[lane];

    for (int e = warp; e < EE; e += nw) {
        int s = src[e];
        int d = dst[e];
        float acc = bb;
#pragma unroll
        for (int v = 0; v < 6; v++) acc = fmaf(ea[e * 6 + v], w[v], acc);
        acc = fmaxf(acc, 0.f);
        float msg = x[s] * acc;
        atomicAdd(&g_agg1[d * CC + lane], msg);
        if (lane == 0) atomicAdd(&g_cnt[d], 1.0f);
    }
}

// ---------------------------------------------------------------------------
// Layer 1 node pass: h1 = relu(agg/max(cnt,1) + x*root1 + bias1)
// ---------------------------------------------------------------------------
__global__ void node1_kernel(const float* __restrict__ x,
                             const float* __restrict__ root1,
                             const float* __restrict__ bias1) {
    int tid = blockIdx.x * blockDim.x + threadIdx.x;
    if (tid >= NN * CC) return;
    int n = tid >> 5;
    int o = tid & 31;
    float inv = 1.0f / fmaxf(g_cnt[n], 1.0f);
    float v = g_agg1[tid] * inv + x[n] * root1[o] + bias1[o];
    g_h1[tid] = fmaxf(v, 0.f);
}

// ---------------------------------------------------------------------------
// Heavy edge pass (layers 2,3, in_c = out_c = 32).
// Warp per edge (grid-stride). Lane o keeps W[:, i*32+o] for all v,i in
// registers (192 regs) — amortized across ~E/nw edges. h[src] row is loaded
// coalesced, broadcast via shfl. 4 partial accumulators for FMA-chain ILP.
// ---------------------------------------------------------------------------
__global__ void __launch_bounds__(128)
edgeH_kernel(const float* __restrict__ h_in,
             const float* __restrict__ ea,
             const int* __restrict__ src,
             const int* __restrict__ dst,
             const float* __restrict__ W,
             const float* __restrict__ b,
             float* __restrict__ agg) {
    int lane = threadIdx.x & 31;
    int warp = (blockIdx.x * blockDim.x + threadIdx.x) >> 5;
    int nw = (gridDim.x * blockDim.x) >> 5;

    // bias in shared (keeps register count for W)
    __shared__ float sb[CC * CC];
    for (int t = threadIdx.x; t < CC * CC; t += blockDim.x) sb[t] = b[t];
    __syncthreads();

    // W column slice in registers: wr[i][v] = W[v*1024 + i*32 + lane]
    float wr[CC][6];
#pragma unroll
    for (int i = 0; i < CC; i++)
#pragma unroll
        for (int v = 0; v < 6; v++)
            wr[i][v] = W[v * (CC * CC) + i * CC + lane];

    for (int e = warp; e < EE; e += nw) {
        int s = src[e];
        int d = dst[e];
        float e0 = ea[e * 6 + 0], e1 = ea[e * 6 + 1], e2 = ea[e * 6 + 2];
        float e3 = ea[e * 6 + 3], e4 = ea[e * 6 + 4], e5 = ea[e * 6 + 5];
        float hv = h_in[s * CC + lane];  // coalesced row load

        float m0 = 0.f, m1 = 0.f, m2 = 0.f, m3 = 0.f;
#pragma unroll
        for (int i = 0; i < CC; i++) {
            float acc = sb[i * CC + lane];
            acc = fmaf(e0, wr[i][0], acc);
            acc = fmaf(e1, wr[i][1], acc);
            acc = fmaf(e2, wr[i][2], acc);
            acc = fmaf(e3, wr[i][3], acc);
            acc = fmaf(e4, wr[i][4], acc);
            acc = fmaf(e5, wr[i][5], acc);
            acc = fmaxf(acc, 0.f);
            float hs = __shfl_sync(0xffffffffu, hv, i);
            if ((i & 3) == 0)      m0 = fmaf(hs, acc, m0);
            else if ((i & 3) == 1) m1 = fmaf(hs, acc, m1);
            else if ((i & 3) == 2) m2 = fmaf(hs, acc, m2);
            else                   m3 = fmaf(hs, acc, m3);
        }
        atomicAdd(&agg[d * CC + lane], (m0 + m1) + (m2 + m3));
    }
}

// ---------------------------------------------------------------------------
// Heavy node pass: h_out = relu(agg/max(cnt,1) + h_in @ root + bias)
// Warp per node; root column in regs, h row broadcast via shfl.
// ---------------------------------------------------------------------------
__global__ void nodeH_kernel(const float* __restrict__ h_in,
                             const float* __restrict__ agg,
                             const float* __restrict__ root,
                             const float* __restrict__ bias,
                             float* __restrict__ h_out) {
    int lane = threadIdx.x & 31;
    int warp = (blockIdx.x * blockDim.x + threadIdx.x) >> 5;
    if (warp >= NN) return;

    float r[CC];
#pragma unroll
    for (int i = 0; i < CC; i++) r[i] = root[i * CC + lane];

    float hv = h_in[warp * CC + lane];
    float a0 = bias[lane], a1 = 0.f, a2 = 0.f, a3 = 0.f;
#pragma unroll
    for (int i = 0; i < CC; i += 4) {
        a0 = fmaf(__shfl_sync(0xffffffffu, hv, i + 0), r[i + 0], a0);
        a1 = fmaf(__shfl_sync(0xffffffffu, hv, i + 1), r[i + 1], a1);
        a2 = fmaf(__shfl_sync(0xffffffffu, hv, i + 2), r[i + 2], a2);
        a3 = fmaf(__shfl_sync(0xffffffffu, hv, i + 3), r[i + 3], a3);
    }
    float inv = 1.0f / fmaxf(g_cnt[warp], 1.0f);
    float v = agg[warp * CC + lane] * inv + (a0 + a1) + (a2 + a3);
    h_out[warp * CC + lane] = fmaxf(v, 0.f);
}

// ---------------------------------------------------------------------------
// CBT: out[i,j] = sum_k |h3[j,k] - h3[i,k]|
// Block = 32(i) x 128(j) tile. j-row in registers; i-rows LDS-broadcast.
// Bank-padded shared staging (stride 33) for conflict-free transposed reads.
// ---------------------------------------------------------------------------
__global__ void __launch_bounds__(128)
cbt_kernel(float* __restrict__ out) {
    __shared__ float si[32 * 33];
    __shared__ float sj[128 * 33];
    int tx = threadIdx.x;
    int j0 = blockIdx.x * 128;
    int i0 = blockIdx.y * 32;

    for (int t = tx; t < 32 * CC; t += 128) {
        int r = t >> 5, c = t & 31;
        si[r * 33 + c] = g_h3[(i0 + r) * CC + c];
    }
    for (int t = tx; t < 128 * CC; t += 128) {
        int r = t >> 5, c = t & 31;
        sj[r * 33 + c] = g_h3[(j0 + r) * CC + c];
    }
    __syncthreads();

    float hj[CC];
#pragma unroll
    for (int k = 0; k < CC; k++) hj[k] = sj[tx * 33 + k];

    for (int i = 0; i < 32; i++) {
        float s0 = 0.f, s1 = 0.f;
#pragma unroll
        for (int k = 0; k < CC; k += 2) {
            s0 += fabsf(si[i * 33 + k] - hj[k]);
            s1 += fabsf(si[i * 33 + k + 1] - hj[k + 1]);
        }
        out[(size_t)(i0 + i) * NN + j0 + tx] = s0 + s1;
    }
}

// ---------------------------------------------------------------------------
// Launch sequence (graph-capturable: kernel launches only)
// ---------------------------------------------------------------------------
extern "C" void kernel_launch(void* const* d_in, const int* in_sizes, int n_in,
                              void* d_out, int out_size) {
    const float* x     = (const float*)d_in[0];
    const float* ea    = (const float*)d_in[1];
    const int*   ei    = (const int*)d_in[2];   // int32! (JAX x64 disabled)
    const float* W1    = (const float*)d_in[3];
    const float* b1    = (const float*)d_in[4];
    const float* root1 = (const float*)d_in[5];
    const float* bias1 = (const float*)d_in[6];
    const float* W2    = (const float*)d_in[7];
    const float* b2    = (const float*)d_in[8];
    const float* root2 = (const float*)d_in[9];
    const float* bias2 = (const float*)d_in[10];
    const float* W3    = (const float*)d_in[11];
    const float* b3    = (const float*)d_in[12];
    const float* root3 = (const float*)d_in[13];
    const float* bias3 = (const float*)d_in[14];
    float* out = (float*)d_out;

    const int* src = ei;
    const int* dst = ei + EE;

    float* agg1; float* agg2; float* agg3;
    float* h1;   float* h2;   float* h3;
    cudaGetSymbolAddress((void**)&agg1, g_agg1);
    cudaGetSymbolAddress((void**)&agg2, g_agg2);
    cudaGetSymbolAddress((void**)&agg3, g_agg3);
    cudaGetSymbolAddress((void**)&h1, g_h1);
    cudaGetSymbolAddress((void**)&h2, g_h2);
    cudaGetSymbolAddress((void**)&h3, g_h3);

    // 1. zero scratch
    zero_kernel<<<(NN * CC + 255) / 256, 256>>>();

    // 2. layer 1
    edge1_kernel<<<256, 256>>>(x, ea, src, dst, W1, b1);
    node1_kernel<<<(NN * CC + 255) / 256, 256>>>(x, root1, bias1);

    // 3. layer 2
    edgeH_kernel<<<592, 128>>>(h1, ea, src, dst, W2, b2, agg2);
    nodeH_kernel<<<(NN * 32 + 255) / 256, 256>>>(h1, agg2, root2, bias2, h2);

    // 4. layer 3
    edgeH_kernel<<<592, 128>>>(h2, ea, src, dst, W3, b3, agg3);
    nodeH_kernel<<<(NN * 32 + 255) / 256, 256>>>(h2, agg3, root3, bias3, h3);

    // 5. CBT all-pairs L1
    dim3 cgrid(NN / 128, NN / 32);
    cbt_kernel<<<cgrid, 128>>>(out);
}

// round 4
// speedup vs baseline: 1.0743x; 1.0743x over previous
#include <cuda_runtime.h>
#include <cstdint>

#define NN 2048
#define EE 65536
#define CC 32

// Packed fp32x2 helpers (sm_103a FFMA2 path — only reachable via PTX)
#define PACK_F32X2(out, lo, hi) \
    asm("mov.b64 %0, {%1, %2};" : "=l"(out) : "f"(lo), "f"(hi))
#define UNPACK_F32X2(lo, hi, in) \
    asm("mov.b64 {%0, %1}, %2;" : "=f"(lo), "=f"(hi) : "l"(in))
#define FMA_F32X2(out, a, b, c) \
    asm("fma.rn.f32x2 %0, %1, %2, %3;" : "=l"(out) : "l"(a), "l"(b), "l"(c))

// Scratch (device globals — no allocation allowed)
__device__ float g_agg1[NN * CC];
__device__ float g_agg2[NN * CC];
__device__ float g_agg3[NN * CC];
__device__ float g_cnt[NN];
__device__ float g_h1[NN * CC];
__device__ float g_h2[NN * CC];
__device__ float g_h3[NN * CC];

// ---------------------------------------------------------------------------
// Zero scratch (must re-run every graph replay)
// ---------------------------------------------------------------------------
__global__ void zero_kernel() {
    int tid = blockIdx.x * blockDim.x + threadIdx.x;
    if (tid < NN * CC) {
        g_agg1[tid] = 0.f;
        g_agg2[tid] = 0.f;
        g_agg3[tid] = 0.f;
    }
    if (tid < NN) g_cnt[tid] = 0.f;
}

// ---------------------------------------------------------------------------
// Layer 1 edge pass (in_c = 1): w = relu(ea@W1 + b1); msg = x[src]*w
// ---------------------------------------------------------------------------
__global__ void edge1_kernel(const float* __restrict__ x,
                             const float* __restrict__ ea,
                             const int* __restrict__ src,
                             const int* __restrict__ dst,
                             const float* __restrict__ W1,
                             const float* __restrict__ b1) {
    int lane = threadIdx.x & 31;
    int warp = (blockIdx.x * blockDim.x + threadIdx.x) >> 5;
    int nw = (gridDim.x * blockDim.x) >> 5;

    float w[6];
#pragma unroll
    for (int v = 0; v < 6; v++) w[v] = W1[v * CC + lane];
    float bb = b1[lane];

    for (int e = warp; e < EE; e += nw) {
        int s = src[e];
        int d = dst[e];
        float acc = bb;
#pragma unroll
        for (int v = 0; v < 6; v++) acc = fmaf(ea[e * 6 + v], w[v], acc);
        acc = fmaxf(acc, 0.f);
        float msg = x[s] * acc;
        atomicAdd(&g_agg1[d * CC + lane], msg);
        if (lane == 0) atomicAdd(&g_cnt[d], 1.0f);
    }
}

// ---------------------------------------------------------------------------
// Layer 1 node pass: h1 = relu(agg/max(cnt,1) + x*root1 + bias1)
// ---------------------------------------------------------------------------
__global__ void node1_kernel(const float* __restrict__ x,
                             const float* __restrict__ root1,
                             const float* __restrict__ bias1) {
    int tid = blockIdx.x * blockDim.x + threadIdx.x;
    if (tid >= NN * CC) return;
    int n = tid >> 5;
    int o = tid & 31;
    float inv = 1.0f / fmaxf(g_cnt[n], 1.0f);
    float v = g_agg1[tid] * inv + x[n] * root1[o] + bias1[o];
    g_h1[tid] = fmaxf(v, 0.f);
}

// ---------------------------------------------------------------------------
// Heavy edge pass (layers 2,3): EDGE SPLIT across a pair of warps.
// Warp parity selects i-half ([0,16) or [16,32)); each warp keeps its W slice
// packed as f32x2 pairs in registers (48 u64 = 96 regs) and uses FFMA2 for
// the edge MLP. Both warps atomicAdd their partial message. 3 CTAs/SM.
// ---------------------------------------------------------------------------
__global__ void __launch_bounds__(128, 3)
edgeH_kernel(const float* __restrict__ h_in,
             const float* __restrict__ ea,
             const int* __restrict__ src,
             const int* __restrict__ dst,
             const float* __restrict__ W,
             const float* __restrict__ b,
             float* __restrict__ agg) {
    int lane = threadIdx.x & 31;
    int wg = (blockIdx.x * blockDim.x + threadIdx.x) >> 5;   // global warp id
    int nw = (gridDim.x * blockDim.x) >> 5;                  // total warps (even)
    int half = wg & 1;                                        // which i-half
    int ibase = half << 4;

    // Packed bias in shared: sb2[t*32+l] = (b[2t*32+l], b[(2t+1)*32+l]), t=0..15
    __shared__ uint64_t sb2[16 * 32];
    for (int p = threadIdx.x; p < 16 * 32; p += 128) {
        int t = p >> 5, l = p & 31;
        float lo = b[(2 * t) * CC + l];
        float hi = b[(2 * t + 1) * CC + l];
        uint64_t pk;
        PACK_F32X2(pk, lo, hi);
        sb2[p] = pk;
    }
    __syncthreads();

    // W slice packed: wr2[t][v] = (W[v,ibase+2t,lane], W[v,ibase+2t+1,lane])
    uint64_t wr2[8][6];
#pragma unroll
    for (int t = 0; t < 8; t++)
#pragma unroll
        for (int v = 0; v < 6; v++) {
            float lo = W[v * (CC * CC) + (ibase + 2 * t) * CC + lane];
            float hi = W[v * (CC * CC) + (ibase + 2 * t + 1) * CC + lane];
            PACK_F32X2(wr2[t][v], lo, hi);
        }

    for (int e = (wg >> 1); e < EE; e += (nw >> 1)) {
        int s = src[e];
        int d = dst[e];
        float hv = h_in[s * CC + lane];  // coalesced row load

        // Broadcast-packed edge attrs
        uint64_t ep[6];
#pragma unroll
        for (int v = 0; v < 6; v++) {
            float evv = ea[e * 6 + v];
            PACK_F32X2(ep[v], evv, evv);
        }

        float m0 = 0.f, m1 = 0.f, m2 = 0.f, m3 = 0.f;
#pragma unroll
        for (int t = 0; t < 8; t++) {
            uint64_t acc = sb2[(half * 8 + t) * 32 + lane];
            FMA_F32X2(acc, ep[0], wr2[t][0], acc);
            FMA_F32X2(acc, ep[1], wr2[t][1], acc);
            FMA_F32X2(acc, ep[2], wr2[t][2], acc);
            FMA_F32X2(acc, ep[3], wr2[t][3], acc);
            FMA_F32X2(acc, ep[4], wr2[t][4], acc);
            FMA_F32X2(acc, ep[5], wr2[t][5], acc);
            float a0, a1;
            UNPACK_F32X2(a0, a1, acc);
            a0 = fmaxf(a0, 0.f);
            a1 = fmaxf(a1, 0.f);
            float h0 = __shfl_sync(0xffffffffu, hv, ibase + 2 * t);
            float h1 = __shfl_sync(0xffffffffu, hv, ibase + 2 * t + 1);
            if (t & 1) {
                m2 = fmaf(h0, a0, m2);
                m3 = fmaf(h1, a1, m3);
            } else {
                m0 = fmaf(h0, a0, m0);
                m1 = fmaf(h1, a1, m1);
            }
        }
        atomicAdd(&agg[d * CC + lane], (m0 + m1) + (m2 + m3));
    }
}

// ---------------------------------------------------------------------------
// Heavy node pass: h_out = relu(agg/max(cnt,1) + h_in @ root + bias)
// ---------------------------------------------------------------------------
__global__ void nodeH_kernel(const float* __restrict__ h_in,
                             const float* __restrict__ agg,
                             const float* __restrict__ root,
                             const float* __restrict__ bias,
                             float* __restrict__ h_out) {
    int lane = threadIdx.x & 31;
    int warp = (blockIdx.x * blockDim.x + threadIdx.x) >> 5;
    if (warp >= NN) return;

    float r[CC];
#pragma unroll
    for (int i = 0; i < CC; i++) r[i] = root[i * CC + lane];

    float hv = h_in[warp * CC + lane];
    float a0 = bias[lane], a1 = 0.f, a2 = 0.f, a3 = 0.f;
#pragma unroll
    for (int i = 0; i < CC; i += 4) {
        a0 = fmaf(__shfl_sync(0xffffffffu, hv, i + 0), r[i + 0], a0);
        a1 = fmaf(__shfl_sync(0xffffffffu, hv, i + 1), r[i + 1], a1);
        a2 = fmaf(__shfl_sync(0xffffffffu, hv, i + 2), r[i + 2], a2);
        a3 = fmaf(__shfl_sync(0xffffffffu, hv, i + 3), r[i + 3], a3);
    }
    float inv = 1.0f / fmaxf(g_cnt[warp], 1.0f);
    float v = agg[warp * CC + lane] * inv + (a0 + a1) + (a2 + a3);
    h_out[warp * CC + lane] = fmaxf(v, 0.f);
}

// ---------------------------------------------------------------------------
// CBT: out[i,j] = sum_k |h3[j,k] - h3[i,k]|
// ---------------------------------------------------------------------------
__global__ void __launch_bounds__(128)
cbt_kernel(float* __restrict__ out) {
    __shared__ float si[32 * 33];
    __shared__ float sj[128 * 33];
    int tx = threadIdx.x;
    int j0 = blockIdx.x * 128;
    int i0 = blockIdx.y * 32;

    for (int t = tx; t < 32 * CC; t += 128) {
        int r = t >> 5, c = t & 31;
        si[r * 33 + c] = g_h3[(i0 + r) * CC + c];
    }
    for (int t = tx; t < 128 * CC; t += 128) {
        int r = t >> 5, c = t & 31;
        sj[r * 33 + c] = g_h3[(j0 + r) * CC + c];
    }
    __syncthreads();

    float hj[CC];
#pragma unroll
    for (int k = 0; k < CC; k++) hj[k] = sj[tx * 33 + k];

    for (int i = 0; i < 32; i++) {
        float s0 = 0.f, s1 = 0.f;
#pragma unroll
        for (int k = 0; k < CC; k += 2) {
            s0 += fabsf(si[i * 33 + k] - hj[k]);
            s1 += fabsf(si[i * 33 + k + 1] - hj[k + 1]);
        }
        out[(size_t)(i0 + i) * NN + j0 + tx] = s0 + s1;
    }
}

// ---------------------------------------------------------------------------
// Launch sequence (graph-capturable: kernel launches only)
// ---------------------------------------------------------------------------
extern "C" void kernel_launch(void* const* d_in, const int* in_sizes, int n_in,
                              void* d_out, int out_size) {
    const float* x     = (const float*)d_in[0];
    const float* ea    = (const float*)d_in[1];
    const int*   ei    = (const int*)d_in[2];   // int32 (JAX x64 disabled)
    const float* W1    = (const float*)d_in[3];
    const float* b1    = (const float*)d_in[4];
    const float* root1 = (const float*)d_in[5];
    const float* bias1 = (const float*)d_in[6];
    const float* W2    = (const float*)d_in[7];
    const float* b2    = (const float*)d_in[8];
    const float* root2 = (const float*)d_in[9];
    const float* bias2 = (const float*)d_in[10];
    const float* W3    = (const float*)d_in[11];
    const float* b3    = (const float*)d_in[12];
    const float* root3 = (const float*)d_in[13];
    const float* bias3 = (const float*)d_in[14];
    float* out = (float*)d_out;

    const int* src = ei;
    const int* dst = ei + EE;

    float* agg1; float* agg2; float* agg3;
    float* h1;   float* h2;   float* h3;
    cudaGetSymbolAddress((void**)&agg1, g_agg1);
    cudaGetSymbolAddress((void**)&agg2, g_agg2);
    cudaGetSymbolAddress((void**)&agg3, g_agg3);
    cudaGetSymbolAddress((void**)&h1, g_h1);
    cudaGetSymbolAddress((void**)&h2, g_h2);
    cudaGetSymbolAddress((void**)&h3, g_h3);

    // 1. zero scratch
    zero_kernel<<<(NN * CC + 255) / 256, 256>>>();

    // 2. layer 1
    edge1_kernel<<<256, 256>>>(x, ea, src, dst, W1, b1);
    node1_kernel<<<(NN * CC + 255) / 256, 256>>>(x, root1, bias1);

    // 3. layer 2  (444 blocks = 3 CTAs × 148 SMs, one wave)
    edgeH_kernel<<<444, 128>>>(h1, ea, src, dst, W2, b2, agg2);
    nodeH_kernel<<<(NN * 32 + 255) / 256, 256>>>(h1, agg2, root2, bias2, h2);

    // 4. layer 3
    edgeH_kernel<<<444, 128>>>(h2, ea, src, dst, W3, b3, agg3);
    nodeH_kernel<<<(NN * 32 + 255) / 256, 256>>>(h2, agg3, root3, bias3, h3);

    // 5. CBT all-pairs L1
    dim3 cgrid(NN / 128, NN / 32);
    cbt_kernel<<<cgrid, 128>>>(out);
}

// round 5
// speedup vs baseline: 1.1281x; 1.0500x over previous
#include <cuda_runtime.h>
#include <cstdint>

#define NN 2048
#define EE 65536
#define CC 32

// Packed fp32x2 helpers (sm_103a FFMA2 path — only reachable via PTX)
#define PACK_F32X2(out, lo, hi) \
    asm("mov.b64 %0, {%1, %2};" : "=l"(out) : "f"(lo), "f"(hi))
#define UNPACK_F32X2(lo, hi, in) \
    asm("mov.b64 {%0, %1}, %2;" : "=f"(lo), "=f"(hi) : "l"(in))
#define FMA_F32X2(out, a, b, c) \
    asm("fma.rn.f32x2 %0, %1, %2, %3;" : "=l"(out) : "l"(a), "l"(b), "l"(c))

// Scratch (device globals — no allocation allowed)
__device__ float g_agg1[NN * CC];
__device__ float g_agg2[NN * CC];
__device__ float g_agg3[NN * CC];
__device__ float g_cnt[NN];
__device__ float g_h1[NN * CC];
__device__ float g_h2[NN * CC];
__device__ float g_h3[NN * CC];

// ---------------------------------------------------------------------------
// Zero scratch (must re-run every graph replay)
// ---------------------------------------------------------------------------
__global__ void zero_kernel() {
    int tid = blockIdx.x * blockDim.x + threadIdx.x;
    if (tid < NN * CC) {
        g_agg1[tid] = 0.f;
        g_agg2[tid] = 0.f;
        g_agg3[tid] = 0.f;
    }
    if (tid < NN) g_cnt[tid] = 0.f;
}

// ---------------------------------------------------------------------------
// Layer 1 edge pass (in_c = 1): w = relu(ea@W1 + b1); msg = x[src]*w
// ---------------------------------------------------------------------------
__global__ void edge1_kernel(const float* __restrict__ x,
                             const float* __restrict__ ea,
                             const int* __restrict__ src,
                             const int* __restrict__ dst,
                             const float* __restrict__ W1,
                             const float* __restrict__ b1) {
    int lane = threadIdx.x & 31;
    int warp = (blockIdx.x * blockDim.x + threadIdx.x) >> 5;
    int nw = (gridDim.x * blockDim.x) >> 5;

    float w[6];
#pragma unroll
    for (int v = 0; v < 6; v++) w[v] = W1[v * CC + lane];
    float bb = b1[lane];

    for (int e = warp; e < EE; e += nw) {
        int s = src[e];
        int d = dst[e];
        float acc = bb;
#pragma unroll
        for (int v = 0; v < 6; v++) acc = fmaf(ea[e * 6 + v], w[v], acc);
        acc = fmaxf(acc, 0.f);
        float msg = x[s] * acc;
        atomicAdd(&g_agg1[d * CC + lane], msg);
        if (lane == 0) atomicAdd(&g_cnt[d], 1.0f);
    }
}

// ---------------------------------------------------------------------------
// Layer 1 node pass: h1 = relu(agg/max(cnt,1) + x*root1 + bias1)
// ---------------------------------------------------------------------------
__global__ void node1_kernel(const float* __restrict__ x,
                             const float* __restrict__ root1,
                             const float* __restrict__ bias1) {
    int tid = blockIdx.x * blockDim.x + threadIdx.x;
    if (tid >= NN * CC) return;
    int n = tid >> 5;
    int o = tid & 31;
    float inv = 1.0f / fmaxf(g_cnt[n], 1.0f);
    float v = g_agg1[tid] * inv + x[n] * root1[o] + bias1[o];
    g_h1[tid] = fmaxf(v, 0.f);
}

// ---------------------------------------------------------------------------
// Heavy edge pass (layers 2,3): 2-warp split per edge, FFMA2 MLP, W + bias
// in registers, software-pipelined loads:
//   - src/dst/ea for edge k+1 prefetched while computing edge k
//   - h gather for edge k issued at top of body (s known from prefetch),
//     latency covered by the 48-FFMA2 MLP block
// ---------------------------------------------------------------------------
__global__ void __launch_bounds__(128, 3)
edgeH_kernel(const float* __restrict__ h_in,
             const float* __restrict__ ea,
             const int* __restrict__ src,
             const int* __restrict__ dst,
             const float* __restrict__ W,
             const float* __restrict__ b,
             float* __restrict__ agg) {
    int lane = threadIdx.x & 31;
    int wg = (blockIdx.x * blockDim.x + threadIdx.x) >> 5;   // global warp id
    int nw = (gridDim.x * blockDim.x) >> 5;                  // total warps (even)
    int half = wg & 1;                                        // which i-half
    int ibase = half << 4;
    int estride = nw >> 1;

    // W slice packed: wr2[t][v] = (W[v,ibase+2t,lane], W[v,ibase+2t+1,lane])
    uint64_t wr2[8][6];
#pragma unroll
    for (int t = 0; t < 8; t++)
#pragma unroll
        for (int v = 0; v < 6; v++) {
            float lo = W[v * (CC * CC) + (ibase + 2 * t) * CC + lane];
            float hi = W[v * (CC * CC) + (ibase + 2 * t + 1) * CC + lane];
            PACK_F32X2(wr2[t][v], lo, hi);
        }
    // bias packed in registers
    uint64_t bb2[8];
#pragma unroll
    for (int t = 0; t < 8; t++) {
        float lo = b[(ibase + 2 * t) * CC + lane];
        float hi = b[(ibase + 2 * t + 1) * CC + lane];
        PACK_F32X2(bb2[t], lo, hi);
    }

    const float2* ea2 = (const float2*)ea;   // ea row = 3 float2 (24B, 8B-aligned)

    int e = wg >> 1;
    if (e >= EE) return;

    // preload edge e
    int s_cur = src[e];
    int d_cur = dst[e];
    float2 a0 = ea2[e * 3 + 0];
    float2 a1 = ea2[e * 3 + 1];
    float2 a2 = ea2[e * 3 + 2];

    while (true) {
        // issue h gather for current edge ASAP
        float hv = h_in[s_cur * CC + lane];

        // prefetch next edge's scalars (warp-uniform branch)
        int e_next = e + estride;
        int s_nxt = 0, d_nxt = 0;
        float2 n0 = make_float2(0.f, 0.f), n1 = n0, n2 = n0;
        bool has_next = (e_next < EE);
        if (has_next) {
            s_nxt = src[e_next];
            d_nxt = dst[e_next];
            n0 = ea2[e_next * 3 + 0];
            n1 = ea2[e_next * 3 + 1];
            n2 = ea2[e_next * 3 + 2];
        }

        // broadcast-pack current edge attrs
        uint64_t ep0, ep1, ep2, ep3, ep4, ep5;
        PACK_F32X2(ep0, a0.x, a0.x);
        PACK_F32X2(ep1, a0.y, a0.y);
        PACK_F32X2(ep2, a1.x, a1.x);
        PACK_F32X2(ep3, a1.y, a1.y);
        PACK_F32X2(ep4, a2.x, a2.x);
        PACK_F32X2(ep5, a2.y, a2.y);

        float m0 = 0.f, m1 = 0.f, m2 = 0.f, m3 = 0.f;
#pragma unroll
        for (int t = 0; t < 8; t++) {
            uint64_t acc = bb2[t];
            FMA_F32X2(acc, ep0, wr2[t][0], acc);
            FMA_F32X2(acc, ep1, wr2[t][1], acc);
            FMA_F32X2(acc, ep2, wr2[t][2], acc);
            FMA_F32X2(acc, ep3, wr2[t][3], acc);
            FMA_F32X2(acc, ep4, wr2[t][4], acc);
            FMA_F32X2(acc, ep5, wr2[t][5], acc);
            float w0, w1;
            UNPACK_F32X2(w0, w1, acc);
            w0 = fmaxf(w0, 0.f);
            w1 = fmaxf(w1, 0.f);
            float h0 = __shfl_sync(0xffffffffu, hv, ibase + 2 * t);
            float h1 = __shfl_sync(0xffffffffu, hv, ibase + 2 * t + 1);
            if (t & 1) {
                m2 = fmaf(h0, w0, m2);
                m3 = fmaf(h1, w1, m3);
            } else {
                m0 = fmaf(h0, w0, m0);
                m1 = fmaf(h1, w1, m1);
            }
        }
        atomicAdd(&agg[d_cur * CC + lane], (m0 + m1) + (m2 + m3));

        if (!has_next) break;
        e = e_next;
        s_cur = s_nxt;
        d_cur = d_nxt;
        a0 = n0; a1 = n1; a2 = n2;
    }
}

// ---------------------------------------------------------------------------
// Heavy node pass: h_out = relu(agg/max(cnt,1) + h_in @ root + bias)
// ---------------------------------------------------------------------------
__global__ void nodeH_kernel(const float* __restrict__ h_in,
                             const float* __restrict__ agg,
                             const float* __restrict__ root,
                             const float* __restrict__ bias,
                             float* __restrict__ h_out) {
    int lane = threadIdx.x & 31;
    int warp = (blockIdx.x * blockDim.x + threadIdx.x) >> 5;
    if (warp >= NN) return;

    float r[CC];
#pragma unroll
    for (int i = 0; i < CC; i++) r[i] = root[i * CC + lane];

    float hv = h_in[warp * CC + lane];
    float a0 = bias[lane], a1 = 0.f, a2 = 0.f, a3 = 0.f;
#pragma unroll
    for (int i = 0; i < CC; i += 4) {
        a0 = fmaf(__shfl_sync(0xffffffffu, hv, i + 0), r[i + 0], a0);
        a1 = fmaf(__shfl_sync(0xffffffffu, hv, i + 1), r[i + 1], a1);
        a2 = fmaf(__shfl_sync(0xffffffffu, hv, i + 2), r[i + 2], a2);
        a3 = fmaf(__shfl_sync(0xffffffffu, hv, i + 3), r[i + 3], a3);
    }
    float inv = 1.0f / fmaxf(g_cnt[warp], 1.0f);
    float v = agg[warp * CC + lane] * inv + (a0 + a1) + (a2 + a3);
    h_out[warp * CC + lane] = fmaxf(v, 0.f);
}

// ---------------------------------------------------------------------------
// CBT: out[i,j] = sum_k |h3[j,k] - h3[i,k]|
// ---------------------------------------------------------------------------
__global__ void __launch_bounds__(128)
cbt_kernel(float* __restrict__ out) {
    __shared__ float si[32 * 33];
    __shared__ float sj[128 * 33];
    int tx = threadIdx.x;
    int j0 = blockIdx.x * 128;
    int i0 = blockIdx.y * 32;

    for (int t = tx; t < 32 * CC; t += 128) {
        int r = t >> 5, c = t & 31;
        si[r * 33 + c] = g_h3[(i0 + r) * CC + c];
    }
    for (int t = tx; t < 128 * CC; t += 128) {
        int r = t >> 5, c = t & 31;
        sj[r * 33 + c] = g_h3[(j0 + r) * CC + c];
    }
    __syncthreads();

    float hj[CC];
#pragma unroll
    for (int k = 0; k < CC; k++) hj[k] = sj[tx * 33 + k];

    for (int i = 0; i < 32; i++) {
        float s0 = 0.f, s1 = 0.f;
#pragma unroll
        for (int k = 0; k < CC; k += 2) {
            s0 += fabsf(si[i * 33 + k] - hj[k]);
            s1 += fabsf(si[i * 33 + k + 1] - hj[k + 1]);
        }
        out[(size_t)(i0 + i) * NN + j0 + tx] = s0 + s1;
    }
}

// ---------------------------------------------------------------------------
// Launch sequence (graph-capturable: kernel launches only)
// ---------------------------------------------------------------------------
extern "C" void kernel_launch(void* const* d_in, const int* in_sizes, int n_in,
                              void* d_out, int out_size) {
    const float* x     = (const float*)d_in[0];
    const float* ea    = (const float*)d_in[1];
    const int*   ei    = (const int*)d_in[2];   // int32 (JAX x64 disabled)
    const float* W1    = (const float*)d_in[3];
    const float* b1    = (const float*)d_in[4];
    const float* root1 = (const float*)d_in[5];
    const float* bias1 = (const float*)d_in[6];
    const float* W2    = (const float*)d_in[7];
    const float* b2    = (const float*)d_in[8];
    const float* root2 = (const float*)d_in[9];
    const float* bias2 = (const float*)d_in[10];
    const float* W3    = (const float*)d_in[11];
    const float* b3    = (const float*)d_in[12];
    const float* root3 = (const float*)d_in[13];
    const float* bias3 = (const float*)d_in[14];
    float* out = (float*)d_out;

    const int* src = ei;
    const int* dst = ei + EE;

    float* agg1; float* agg2; float* agg3;
    float* h1;   float* h2;   float* h3;
    cudaGetSymbolAddress((void**)&agg1, g_agg1);
    cudaGetSymbolAddress((void**)&agg2, g_agg2);
    cudaGetSymbolAddress((void**)&agg3, g_agg3);
    cudaGetSymbolAddress((void**)&h1, g_h1);
    cudaGetSymbolAddress((void**)&h2, g_h2);
    cudaGetSymbolAddress((void**)&h3, g_h3);

    // 1. zero scratch
    zero_kernel<<<(NN * CC + 255) / 256, 256>>>();

    // 2. layer 1
    edge1_kernel<<<256, 256>>>(x, ea, src, dst, W1, b1);
    node1_kernel<<<(NN * CC + 255) / 256, 256>>>(x, root1, bias1);

    // 3. layer 2  (444 blocks = 3 CTAs × 148 SMs)
    edgeH_kernel<<<444, 128>>>(h1, ea, src, dst, W2, b2, agg2);
    nodeH_kernel<<<(NN * 32 + 255) / 256, 256>>>(h1, agg2, root2, bias2, h2);

    // 4. layer 3
    edgeH_kernel<<<444, 128>>>(h2, ea, src, dst, W3, b3, agg3);
    nodeH_kernel<<<(NN * 32 + 255) / 256, 256>>>(h2, agg3, root3, bias3, h3);

    // 5. CBT all-pairs L1
    dim3 cgrid(NN / 128, NN / 32);
    cbt_kernel<<<cgrid, 128>>>(out);
}